// round 6
// baseline (speedup 1.0000x reference)
#include <cuda_runtime.h>

// ---------------------------------------------------------------------------
// VQ-EMA layer, GB300 (sm_103a)  — round 5
// Inputs : x [16,1024,256] f32, embed_w [1024,256] f32,
//          ema_cluster_size [1024] f32, ema_w [1024,256] f32
// Output : concat( quantized[16*1024*256], loss[1], embed_new[1024*256],
//                  cs[1024], ema_w_new[1024*256] )
// ---------------------------------------------------------------------------

constexpr int Bc = 16, Tc = 1024, Dc = 256, Kc = 1024;
constexpr int Nrows = Bc * Tc;            // 16384
constexpr int TM = 128;                   // rows per block
constexpr int NPASS = 8;                  // col passes (128 cols each)

constexpr float DECAYF = 0.99f;
constexpr float OMDF   = 0.01f;
constexpr float EPSF   = 1e-5f;
constexpr float KEPSF  = 0.01024f;        // K * EPS

// smem (words): x tile pair-packed + argmin reduction area
constexpr int SX_STRIDE = 514;            // 514%32==2 -> conflict-free a-LDS
constexpr int SX_WORDS  = (TM / 2) * SX_STRIDE;   // 32896
constexpr int RED_WORDS = 2048 + 2048 + 128;      // sMin + sIdx + sFin
constexpr int SMEM_BYTES = (SX_WORDS + RED_WORDS) * 4;  // 148480 B

// ----- scratch (device globals; no allocations allowed) -----
__device__ float g_xsq[Nrows];
__device__ float g_wsq[Kc];
__device__ float g_wdup[Kc * Dc * 2];     // (w[c][d], w[c][d]) pairs, 8 MB
__device__ float g_dw[Kc * Dc];
__device__ float g_counts[Kc];
__device__ float g_loss;

// ---------------------------------------------------------------------------
// Kernel 0: row sum-of-squares for x and w; build duplicated w; zero scratch.
// Reduction structure byte-identical to rounds 2/4 -> xsq/wsq bit-identical.
// ---------------------------------------------------------------------------
__global__ void prep_kernel(const float* __restrict__ x,
                            const float* __restrict__ w) {
  int b = blockIdx.x;
  int t = threadIdx.x;
  float v;
  if (b < Nrows) {
    v = x[(size_t)b * Dc + t];
  } else {
    int k = b - Nrows;
    v = w[(size_t)k * Dc + t];
    g_wdup[(size_t)k * 512 + 2 * t]     = v;
    g_wdup[(size_t)k * 512 + 2 * t + 1] = v;
    g_dw[(size_t)k * Dc + t] = 0.0f;
    if (t == 0) g_counts[k] = 0.0f;
    if (t == 1 && k == 0) g_loss = 0.0f;
  }
  float s = v * v;
  #pragma unroll
  for (int o = 16; o; o >>= 1) s += __shfl_down_sync(0xffffffffu, s, o);
  __shared__ float red[8];
  if ((t & 31) == 0) red[t >> 5] = s;
  __syncthreads();
  if (t == 0) {
    float tot = red[0];
    #pragma unroll
    for (int i = 1; i < 8; i++) tot += red[i];
    if (b < Nrows) g_xsq[b] = tot;
    else           g_wsq[b - Nrows] = tot;
  }
}

// ---------------------------------------------------------------------------
// Kernel 1: fused distance GEMM + argmin + gather/scatter epilogue.
//   score[n,k] = fp32( fp32(xsq[n] + wsq[k]) - 2 * dot(x[n], w[k]) )
// dot: single fp32x2 accumulator per (n,k), d ascending, fma.rn.f32x2 ->
// bit-identical to rounds 2/4. Tie -> lowest k.
// x tile in smem (a-operand, LDS.64, stride 514 conflict-free).
// b-operand streams from L2 via LDG.128 of pre-duplicated g_wdup —
// no smem traffic for w, no per-chunk barriers. Microtile 4 row-pairs x 8 cols.
// ---------------------------------------------------------------------------

#define VQ_STEP(BB, OFS)                                                       \
  {                                                                            \
    unsigned long long a0_[4], a1_[4];                                         \
    a0_[0] = *reinterpret_cast<const unsigned long long*>(pa0 + (OFS));        \
    a0_[1] = *reinterpret_cast<const unsigned long long*>(pa1 + (OFS));        \
    a0_[2] = *reinterpret_cast<const unsigned long long*>(pa2 + (OFS));        \
    a0_[3] = *reinterpret_cast<const unsigned long long*>(pa3 + (OFS));        \
    a1_[0] = *reinterpret_cast<const unsigned long long*>(pa0 + (OFS) + 2);    \
    a1_[1] = *reinterpret_cast<const unsigned long long*>(pa1 + (OFS) + 2);    \
    a1_[2] = *reinterpret_cast<const unsigned long long*>(pa2 + (OFS) + 2);    \
    a1_[3] = *reinterpret_cast<const unsigned long long*>(pa3 + (OFS) + 2);    \
    _Pragma("unroll")                                                          \
    for (int j_ = 0; j_ < 8; j_++) {                                           \
      _Pragma("unroll")                                                        \
      for (int i_ = 0; i_ < 4; i_++)                                           \
        asm("fma.rn.f32x2 %0, %1, %2, %0;"                                     \
            : "+l"(acc[i_][j_]) : "l"(a0_[i_]), "l"(BB[j_].x));                \
    }                                                                          \
    _Pragma("unroll")                                                          \
    for (int j_ = 0; j_ < 8; j_++) {                                           \
      _Pragma("unroll")                                                        \
      for (int i_ = 0; i_ < 4; i_++)                                           \
        asm("fma.rn.f32x2 %0, %1, %2, %0;"                                     \
            : "+l"(acc[i_][j_]) : "l"(a1_[i_]), "l"(BB[j_].y));                \
    }                                                                          \
  }

#define VQ_PREF(BB, DPN)                                                       \
  {                                                                            \
    int dn_ = (DPN) & 127;                                                     \
    _Pragma("unroll")                                                          \
    for (int j_ = 0; j_ < 8; j_++) BB[j_] = bq[j_][dn_];                       \
  }

__global__ void __launch_bounds__(256, 1)
argmin_kernel(const float* __restrict__ x, const float* __restrict__ w,
              float* __restrict__ outQ) {
  extern __shared__ float smem[];
  float* sx = smem;                 // x tile, pair-packed (x0[d],x1[d]) at 2d

  const int tid = threadIdx.x;
  const int tm = tid & 15;          // row-pair group (pairs tm, tm+16, +32, +48)
  const int tk = tid >> 4;          // col group
  const int rowBase = blockIdx.x * TM;

  // ---- load x tile: sx[pr*514 + par + 2*d] = x[rowBase + 2*pr + par][d]
  {
    int r    = tid >> 1;            // 0..127
    int half = tid & 1;             // which 128-d half
    int pr   = r >> 1, par = r & 1;
    const float4* src =
        reinterpret_cast<const float4*>(x + (size_t)(rowBase + r) * Dc) + half * 32;
    float* dst = sx + pr * SX_STRIDE + par;
    #pragma unroll
    for (int q = 0; q < 32; q++) {
      float4 v = src[q];
      int d = half * 128 + q * 4;
      dst[2 * d + 0] = v.x;
      dst[2 * d + 2] = v.y;
      dst[2 * d + 4] = v.z;
      dst[2 * d + 6] = v.w;
    }
  }

  float xsqv[8];
  float best[8];
  int   bidx[8];
  #pragma unroll
  for (int i = 0; i < 4; i++) {
    int pr = tm + 16 * i;
    xsqv[2 * i + 0] = g_xsq[rowBase + 2 * pr + 0];
    xsqv[2 * i + 1] = g_xsq[rowBase + 2 * pr + 1];
    best[2 * i] = best[2 * i + 1] = 3.4e38f;
    bidx[2 * i] = bidx[2 * i + 1] = 0;
  }

  const float* pa0 = sx + (tm + 0)  * SX_STRIDE;
  const float* pa1 = sx + (tm + 16) * SX_STRIDE;
  const float* pa2 = sx + (tm + 32) * SX_STRIDE;
  const float* pa3 = sx + (tm + 48) * SX_STRIDE;

  __syncthreads();   // x tile visible to all

  for (int pass = 0; pass < NPASS; pass++) {
    const int c0 = pass * 128 + tk;          // cols c0 + 16*j, j=0..7
    const ulonglong2* bq[8];
    float wsqv[8];
    #pragma unroll
    for (int j = 0; j < 8; j++) {
      int c = c0 + 16 * j;
      bq[j] = reinterpret_cast<const ulonglong2*>(g_wdup + (size_t)c * 512);
      wsqv[j] = g_wsq[c];
    }

    unsigned long long acc[4][8];
    #pragma unroll
    for (int i = 0; i < 4; i++)
      #pragma unroll
      for (int j = 0; j < 8; j++) acc[i][j] = 0ull;   // packed (0.f, 0.f)

    ulonglong2 bb0[8], bb1[8];
    VQ_PREF(bb0, 0);
    VQ_PREF(bb1, 1);

    for (int dp = 0; dp < 128; dp += 2) {
      VQ_STEP(bb0, 4 * dp);        // d = 2*dp, 2*dp+1
      VQ_PREF(bb0, dp + 2);
      VQ_STEP(bb1, 4 * dp + 4);    // d = 2*dp+2, 2*dp+3
      VQ_PREF(bb1, dp + 3);
    }

    // ---- scores + running argmin (same fadd chain as rounds 2/4)
    #pragma unroll
    for (int j = 0; j < 8; j++) {
      int c = c0 + 16 * j;
      float wsqc = wsqv[j];
      #pragma unroll
      for (int i = 0; i < 4; i++) {
        float2 dv = *reinterpret_cast<float2*>(&acc[i][j]);
        float r1a = __fadd_rn(xsqv[2 * i + 0], wsqc);
        float s0  = __fadd_rn(r1a, -2.0f * dv.x);
        float r1b = __fadd_rn(xsqv[2 * i + 1], wsqc);
        float s1  = __fadd_rn(r1b, -2.0f * dv.y);
        if (s0 < best[2 * i + 0]) { best[2 * i + 0] = s0; bidx[2 * i + 0] = c; }
        if (s1 < best[2 * i + 1]) { best[2 * i + 1] = s1; bidx[2 * i + 1] = c; }
      }
    }
  }

  // ---- cross-thread (over tk) argmin reduction
  __syncthreads();
  float* sMin = sx + SX_WORDS;                   // [16][128]
  int*   sIdx = reinterpret_cast<int*>(sMin + 2048);
  int*   sFin = reinterpret_cast<int*>(sMin + 4096);  // final idx per row [128]
  #pragma unroll
  for (int i = 0; i < 4; i++) {
    #pragma unroll
    for (int p = 0; p < 2; p++) {
      int r = 2 * (tm + 16 * i) + p;
      sMin[tk * 128 + r] = best[2 * i + p];
      sIdx[tk * 128 + r] = bidx[2 * i + p];
    }
  }
  __syncthreads();
  if (tid < 128) {
    float bv = sMin[tid];
    int   bi = sIdx[tid];
    #pragma unroll
    for (int t2 = 1; t2 < 16; t2++) {
      float v = sMin[t2 * 128 + tid];
      int   ii = sIdx[t2 * 128 + tid];
      if (v < bv || (v == bv && ii < bi)) { bv = v; bi = ii; }
    }
    sFin[tid] = bi;
    atomicAdd(&g_counts[bi], 1.0f);
  }
  __syncthreads();

  // ---- epilogue: gather quantized rows, loss partial, dw scatter.
  float lsum = 0.0f;
  {
    int q = tid & 63, rg = tid >> 6;
    #pragma unroll 4
    for (int it = 0; it < 32; ++it) {
      int row = rg * 32 + it;
      int k = sFin[row];
      float4 wv = *reinterpret_cast<const float4*>(w + (size_t)k * Dc + 4 * q);
      int pr = row >> 1, par = row & 1;
      const float* xs = sx + pr * SX_STRIDE + par + 8 * q;
      float x0 = xs[0], x1 = xs[2], x2 = xs[4], x3 = xs[6];
      *reinterpret_cast<float4*>(outQ + (size_t)(rowBase + row) * Dc + 4 * q) = wv;
      float d0 = x0 - wv.x, d1 = x1 - wv.y, d2 = x2 - wv.z, d3 = x3 - wv.w;
      lsum += d0 * d0 + d1 * d1 + d2 * d2 + d3 * d3;
      float* dwp = g_dw + (size_t)k * Dc + 4 * q;
      atomicAdd(dwp + 0, x0);
      atomicAdd(dwp + 1, x1);
      atomicAdd(dwp + 2, x2);
      atomicAdd(dwp + 3, x3);
    }
  }
  #pragma unroll
  for (int o = 16; o; o >>= 1) lsum += __shfl_down_sync(0xffffffffu, lsum, o);
  __shared__ float red2[8];
  if ((tid & 31) == 0) red2[tid >> 5] = lsum;
  __syncthreads();
  if (tid == 0) {
    float tot = red2[0];
    #pragma unroll
    for (int i = 1; i < 8; i++) tot += red2[i];
    atomicAdd(&g_loss, tot);
  }
}

// ---------------------------------------------------------------------------
// Kernel 2: fused cluster-size EMA + Laplace smoothing + ema_w EMA + embed.
// n = 0.99*sum(ema_cs) + 0.01*Nrows  (sum(counts) == Nrows exactly).
// ---------------------------------------------------------------------------
__global__ void emacs_kernel(const float* __restrict__ ema_cs,
                             const float* __restrict__ ema_w,
                             float* __restrict__ outLoss,
                             float* __restrict__ outEmbed,
                             float* __restrict__ outCS,
                             float* __restrict__ outEmaW) {
  int k = blockIdx.x, d = threadIdx.x;
  __shared__ float red[8];
  __shared__ float s_cs;

  float4 v = reinterpret_cast<const float4*>(ema_cs)[d];
  float s = v.x + v.y + v.z + v.w;
  #pragma unroll
  for (int o = 16; o; o >>= 1) s += __shfl_down_sync(0xffffffffu, s, o);
  if ((d & 31) == 0) red[d >> 5] = s;
  __syncthreads();
  if (d == 0) {
    float S = red[0];
    #pragma unroll
    for (int i = 1; i < 8; i++) S += red[i];
    float n = DECAYF * S + OMDF * (float)Nrows;
    float c = ema_cs[k] * DECAYF + OMDF * g_counts[k];
    float csf = (c + EPSF) / (n + KEPSF) * n;
    s_cs = csf;
    outCS[k] = csf;
    if (k == 0) outLoss[0] = 0.25f * g_loss * (1.0f / 4194304.0f);
  }
  __syncthreads();
  float csv = s_cs;
  size_t i = (size_t)k * Dc + d;
  float ew = ema_w[i] * DECAYF + OMDF * g_dw[i];
  outEmaW[i]  = ew;
  outEmbed[i] = ew / csv;
}

// ---------------------------------------------------------------------------
extern "C" void kernel_launch(void* const* d_in, const int* in_sizes, int n_in,
                              void* d_out, int out_size) {
  const float* x      = (const float*)d_in[0];
  const float* w      = (const float*)d_in[1];
  const float* ema_cs = (const float*)d_in[2];
  const float* ema_w  = (const float*)d_in[3];

  float* out      = (float*)d_out;
  float* outQ     = out;                                   // 4,194,304
  float* outLoss  = out + (size_t)Nrows * Dc;              // 1
  float* outEmbed = outLoss + 1;                           // 262,144
  float* outCS    = outEmbed + (size_t)Kc * Dc;            // 1,024
  float* outEmaW  = outCS + Kc;                            // 262,144

  cudaFuncSetAttribute(argmin_kernel,
                       cudaFuncAttributeMaxDynamicSharedMemorySize, SMEM_BYTES);

  prep_kernel<<<Nrows + Kc, 256>>>(x, w);
  argmin_kernel<<<Nrows / TM, 256, SMEM_BYTES>>>(x, w, outQ);
  emacs_kernel<<<Kc, 256>>>(ema_cs, ema_w, outLoss, outEmbed, outCS, outEmaW);
}

// round 7
// speedup vs baseline: 1.0444x; 1.0444x over previous
#include <cuda_runtime.h>

// ---------------------------------------------------------------------------
// VQ-EMA layer, GB300 (sm_103a)  — round 5
// Inputs : x [16,1024,256] f32, embed_w [1024,256] f32,
//          ema_cluster_size [1024] f32, ema_w [1024,256] f32
// Output : concat( quantized[16*1024*256], loss[1], embed_new[1024*256],
//                  cs[1024], ema_w_new[1024*256] )
// ---------------------------------------------------------------------------

constexpr int Bc = 16, Tc = 1024, Dc = 256, Kc = 1024;
constexpr int Nrows = Bc * Tc;            // 16384
constexpr int TM = 128;                   // rows per block
constexpr int NPASS = 8;                  // col passes (128 cols each)

constexpr float DECAYF = 0.99f;
constexpr float OMDF   = 0.01f;
constexpr float EPSF   = 1e-5f;
constexpr float KEPSF  = 0.01024f;        // K * EPS

// smem (words): x tile pair-packed + argmin reduction area
constexpr int SX_STRIDE = 514;            // 514%32==2 -> conflict-free a-LDS
constexpr int SX_WORDS  = (TM / 2) * SX_STRIDE;   // 32896
constexpr int RED_WORDS = 2048 + 2048 + 128;      // sMin + sIdx + sFin
constexpr int SMEM_BYTES = (SX_WORDS + RED_WORDS) * 4;  // 148480 B

// ----- scratch (device globals; no allocations allowed) -----
__device__ float g_xsq[Nrows];
__device__ float g_wsq[Kc];
__device__ float g_wdup[Kc * Dc * 2];     // (w[c][d], w[c][d]) pairs, 8 MB
__device__ float g_dw[Kc * Dc];
__device__ float g_counts[Kc];
__device__ float g_loss;

// ---------------------------------------------------------------------------
// Kernel 0: row sum-of-squares for x and w; build duplicated w; zero scratch.
// Reduction structure byte-identical to rounds 2/4 -> xsq/wsq bit-identical.
// ---------------------------------------------------------------------------
__global__ void prep_kernel(const float* __restrict__ x,
                            const float* __restrict__ w) {
  int b = blockIdx.x;
  int t = threadIdx.x;
  float v;
  if (b < Nrows) {
    v = x[(size_t)b * Dc + t];
  } else {
    int k = b - Nrows;
    v = w[(size_t)k * Dc + t];
    g_wdup[(size_t)k * 512 + 2 * t]     = v;
    g_wdup[(size_t)k * 512 + 2 * t + 1] = v;
    g_dw[(size_t)k * Dc + t] = 0.0f;
    if (t == 0) g_counts[k] = 0.0f;
    if (t == 1 && k == 0) g_loss = 0.0f;
  }
  float s = v * v;
  #pragma unroll
  for (int o = 16; o; o >>= 1) s += __shfl_down_sync(0xffffffffu, s, o);
  __shared__ float red[8];
  if ((t & 31) == 0) red[t >> 5] = s;
  __syncthreads();
  if (t == 0) {
    float tot = red[0];
    #pragma unroll
    for (int i = 1; i < 8; i++) tot += red[i];
    if (b < Nrows) g_xsq[b] = tot;
    else           g_wsq[b - Nrows] = tot;
  }
}

// ---------------------------------------------------------------------------
// Kernel 1: fused distance GEMM + argmin + gather/scatter epilogue.
//   score[n,k] = fp32( fp32(xsq[n] + wsq[k]) - 2 * dot(x[n], w[k]) )
// dot: single fp32x2 accumulator per (n,k), d ascending, fma.rn.f32x2 ->
// bit-identical to rounds 2/4. Tie -> lowest k.
// x tile in smem (a-operand, LDS.64, stride 514 conflict-free).
// b-operand streams from L2 via LDG.128 of pre-duplicated g_wdup —
// no smem traffic for w, no per-chunk barriers. Microtile 4 row-pairs x 8 cols.
// ---------------------------------------------------------------------------

#define VQ_STEP(BB, OFS)                                                       \
  {                                                                            \
    unsigned long long a0_[4], a1_[4];                                         \
    a0_[0] = *reinterpret_cast<const unsigned long long*>(pa0 + (OFS));        \
    a0_[1] = *reinterpret_cast<const unsigned long long*>(pa1 + (OFS));        \
    a0_[2] = *reinterpret_cast<const unsigned long long*>(pa2 + (OFS));        \
    a0_[3] = *reinterpret_cast<const unsigned long long*>(pa3 + (OFS));        \
    a1_[0] = *reinterpret_cast<const unsigned long long*>(pa0 + (OFS) + 2);    \
    a1_[1] = *reinterpret_cast<const unsigned long long*>(pa1 + (OFS) + 2);    \
    a1_[2] = *reinterpret_cast<const unsigned long long*>(pa2 + (OFS) + 2);    \
    a1_[3] = *reinterpret_cast<const unsigned long long*>(pa3 + (OFS) + 2);    \
    _Pragma("unroll")                                                          \
    for (int j_ = 0; j_ < 8; j_++) {                                           \
      _Pragma("unroll")                                                        \
      for (int i_ = 0; i_ < 4; i_++)                                           \
        asm("fma.rn.f32x2 %0, %1, %2, %0;"                                     \
            : "+l"(acc[i_][j_]) : "l"(a0_[i_]), "l"(BB[j_].x));                \
    }                                                                          \
    _Pragma("unroll")                                                          \
    for (int j_ = 0; j_ < 8; j_++) {                                           \
      _Pragma("unroll")                                                        \
      for (int i_ = 0; i_ < 4; i_++)                                           \
        asm("fma.rn.f32x2 %0, %1, %2, %0;"                                     \
            : "+l"(acc[i_][j_]) : "l"(a1_[i_]), "l"(BB[j_].y));                \
    }                                                                          \
  }

#define VQ_PREF(BB, DPN)                                                       \
  {                                                                            \
    int dn_ = (DPN) & 127;                                                     \
    _Pragma("unroll")                                                          \
    for (int j_ = 0; j_ < 8; j_++) BB[j_] = bq[j_][dn_];                       \
  }

__global__ void __launch_bounds__(256, 1)
argmin_kernel(const float* __restrict__ x, const float* __restrict__ w,
              float* __restrict__ outQ) {
  extern __shared__ float smem[];
  float* sx = smem;                 // x tile, pair-packed (x0[d],x1[d]) at 2d

  const int tid = threadIdx.x;
  const int tm = tid & 15;          // row-pair group (pairs tm, tm+16, +32, +48)
  const int tk = tid >> 4;          // col group
  const int rowBase = blockIdx.x * TM;

  // ---- load x tile: sx[pr*514 + par + 2*d] = x[rowBase + 2*pr + par][d]
  {
    int r    = tid >> 1;            // 0..127
    int half = tid & 1;             // which 128-d half
    int pr   = r >> 1, par = r & 1;
    const float4* src =
        reinterpret_cast<const float4*>(x + (size_t)(rowBase + r) * Dc) + half * 32;
    float* dst = sx + pr * SX_STRIDE + par;
    #pragma unroll
    for (int q = 0; q < 32; q++) {
      float4 v = src[q];
      int d = half * 128 + q * 4;
      dst[2 * d + 0] = v.x;
      dst[2 * d + 2] = v.y;
      dst[2 * d + 4] = v.z;
      dst[2 * d + 6] = v.w;
    }
  }

  float xsqv[8];
  float best[8];
  int   bidx[8];
  #pragma unroll
  for (int i = 0; i < 4; i++) {
    int pr = tm + 16 * i;
    xsqv[2 * i + 0] = g_xsq[rowBase + 2 * pr + 0];
    xsqv[2 * i + 1] = g_xsq[rowBase + 2 * pr + 1];
    best[2 * i] = best[2 * i + 1] = 3.4e38f;
    bidx[2 * i] = bidx[2 * i + 1] = 0;
  }

  const float* pa0 = sx + (tm + 0)  * SX_STRIDE;
  const float* pa1 = sx + (tm + 16) * SX_STRIDE;
  const float* pa2 = sx + (tm + 32) * SX_STRIDE;
  const float* pa3 = sx + (tm + 48) * SX_STRIDE;

  __syncthreads();   // x tile visible to all

  for (int pass = 0; pass < NPASS; pass++) {
    const int c0 = pass * 128 + tk;          // cols c0 + 16*j, j=0..7
    const ulonglong2* bq[8];
    float wsqv[8];
    #pragma unroll
    for (int j = 0; j < 8; j++) {
      int c = c0 + 16 * j;
      bq[j] = reinterpret_cast<const ulonglong2*>(g_wdup + (size_t)c * 512);
      wsqv[j] = g_wsq[c];
    }

    unsigned long long acc[4][8];
    #pragma unroll
    for (int i = 0; i < 4; i++)
      #pragma unroll
      for (int j = 0; j < 8; j++) acc[i][j] = 0ull;   // packed (0.f, 0.f)

    ulonglong2 bb0[8], bb1[8];
    VQ_PREF(bb0, 0);
    VQ_PREF(bb1, 1);

    for (int dp = 0; dp < 128; dp += 2) {
      VQ_STEP(bb0, 4 * dp);        // d = 2*dp, 2*dp+1
      VQ_PREF(bb0, dp + 2);
      VQ_STEP(bb1, 4 * dp + 4);    // d = 2*dp+2, 2*dp+3
      VQ_PREF(bb1, dp + 3);
    }

    // ---- scores + running argmin (same fadd chain as rounds 2/4)
    #pragma unroll
    for (int j = 0; j < 8; j++) {
      int c = c0 + 16 * j;
      float wsqc = wsqv[j];
      #pragma unroll
      for (int i = 0; i < 4; i++) {
        float2 dv = *reinterpret_cast<float2*>(&acc[i][j]);
        float r1a = __fadd_rn(xsqv[2 * i + 0], wsqc);
        float s0  = __fadd_rn(r1a, -2.0f * dv.x);
        float r1b = __fadd_rn(xsqv[2 * i + 1], wsqc);
        float s1  = __fadd_rn(r1b, -2.0f * dv.y);
        if (s0 < best[2 * i + 0]) { best[2 * i + 0] = s0; bidx[2 * i + 0] = c; }
        if (s1 < best[2 * i + 1]) { best[2 * i + 1] = s1; bidx[2 * i + 1] = c; }
      }
    }
  }

  // ---- cross-thread (over tk) argmin reduction
  __syncthreads();
  float* sMin = sx + SX_WORDS;                   // [16][128]
  int*   sIdx = reinterpret_cast<int*>(sMin + 2048);
  int*   sFin = reinterpret_cast<int*>(sMin + 4096);  // final idx per row [128]
  #pragma unroll
  for (int i = 0; i < 4; i++) {
    #pragma unroll
    for (int p = 0; p < 2; p++) {
      int r = 2 * (tm + 16 * i) + p;
      sMin[tk * 128 + r] = best[2 * i + p];
      sIdx[tk * 128 + r] = bidx[2 * i + p];
    }
  }
  __syncthreads();
  if (tid < 128) {
    float bv = sMin[tid];
    int   bi = sIdx[tid];
    #pragma unroll
    for (int t2 = 1; t2 < 16; t2++) {
      float v = sMin[t2 * 128 + tid];
      int   ii = sIdx[t2 * 128 + tid];
      if (v < bv || (v == bv && ii < bi)) { bv = v; bi = ii; }
    }
    sFin[tid] = bi;
    atomicAdd(&g_counts[bi], 1.0f);
  }
  __syncthreads();

  // ---- epilogue: gather quantized rows, loss partial, dw scatter.
  float lsum = 0.0f;
  {
    int q = tid & 63, rg = tid >> 6;
    #pragma unroll 4
    for (int it = 0; it < 32; ++it) {
      int row = rg * 32 + it;
      int k = sFin[row];
      float4 wv = *reinterpret_cast<const float4*>(w + (size_t)k * Dc + 4 * q);
      int pr = row >> 1, par = row & 1;
      const float* xs = sx + pr * SX_STRIDE + par + 8 * q;
      float x0 = xs[0], x1 = xs[2], x2 = xs[4], x3 = xs[6];
      *reinterpret_cast<float4*>(outQ + (size_t)(rowBase + row) * Dc + 4 * q) = wv;
      float d0 = x0 - wv.x, d1 = x1 - wv.y, d2 = x2 - wv.z, d3 = x3 - wv.w;
      lsum += d0 * d0 + d1 * d1 + d2 * d2 + d3 * d3;
      float* dwp = g_dw + (size_t)k * Dc + 4 * q;
      atomicAdd(dwp + 0, x0);
      atomicAdd(dwp + 1, x1);
      atomicAdd(dwp + 2, x2);
      atomicAdd(dwp + 3, x3);
    }
  }
  #pragma unroll
  for (int o = 16; o; o >>= 1) lsum += __shfl_down_sync(0xffffffffu, lsum, o);
  __shared__ float red2[8];
  if ((tid & 31) == 0) red2[tid >> 5] = lsum;
  __syncthreads();
  if (tid == 0) {
    float tot = red2[0];
    #pragma unroll
    for (int i = 1; i < 8; i++) tot += red2[i];
    atomicAdd(&g_loss, tot);
  }
}

// ---------------------------------------------------------------------------
// Kernel 2: fused cluster-size EMA + Laplace smoothing + ema_w EMA + embed.
// n = 0.99*sum(ema_cs) + 0.01*Nrows  (sum(counts) == Nrows exactly).
// ---------------------------------------------------------------------------
__global__ void emacs_kernel(const float* __restrict__ ema_cs,
                             const float* __restrict__ ema_w,
                             float* __restrict__ outLoss,
                             float* __restrict__ outEmbed,
                             float* __restrict__ outCS,
                             float* __restrict__ outEmaW) {
  int k = blockIdx.x, d = threadIdx.x;
  __shared__ float red[8];
  __shared__ float s_cs;

  float4 v = reinterpret_cast<const float4*>(ema_cs)[d];
  float s = v.x + v.y + v.z + v.w;
  #pragma unroll
  for (int o = 16; o; o >>= 1) s += __shfl_down_sync(0xffffffffu, s, o);
  if ((d & 31) == 0) red[d >> 5] = s;
  __syncthreads();
  if (d == 0) {
    float S = red[0];
    #pragma unroll
    for (int i = 1; i < 8; i++) S += red[i];
    float n = DECAYF * S + OMDF * (float)Nrows;
    float c = ema_cs[k] * DECAYF + OMDF * g_counts[k];
    float csf = (c + EPSF) / (n + KEPSF) * n;
    s_cs = csf;
    outCS[k] = csf;
    if (k == 0) outLoss[0] = 0.25f * g_loss * (1.0f / 4194304.0f);
  }
  __syncthreads();
  float csv = s_cs;
  size_t i = (size_t)k * Dc + d;
  float ew = ema_w[i] * DECAYF + OMDF * g_dw[i];
  outEmaW[i]  = ew;
  outEmbed[i] = ew / csv;
}

// ---------------------------------------------------------------------------
extern "C" void kernel_launch(void* const* d_in, const int* in_sizes, int n_in,
                              void* d_out, int out_size) {
  const float* x      = (const float*)d_in[0];
  const float* w      = (const float*)d_in[1];
  const float* ema_cs = (const float*)d_in[2];
  const float* ema_w  = (const float*)d_in[3];

  float* out      = (float*)d_out;
  float* outQ     = out;                                   // 4,194,304
  float* outLoss  = out + (size_t)Nrows * Dc;              // 1
  float* outEmbed = outLoss + 1;                           // 262,144
  float* outCS    = outEmbed + (size_t)Kc * Dc;            // 1,024
  float* outEmaW  = outCS + Kc;                            // 262,144

  cudaFuncSetAttribute(argmin_kernel,
                       cudaFuncAttributeMaxDynamicSharedMemorySize, SMEM_BYTES);

  prep_kernel<<<Nrows + Kc, 256>>>(x, w);
  argmin_kernel<<<Nrows / TM, 256, SMEM_BYTES>>>(x, w, outQ);
  emacs_kernel<<<Kc, 256>>>(ema_cs, ema_w, outLoss, outEmbed, outCS, outEmaW);
}

// round 9
// speedup vs baseline: 1.6974x; 1.6252x over previous
#include <cuda_runtime.h>
#include <cstdint>

// ---------------------------------------------------------------------------
// VQ-EMA layer, GB300 (sm_103a) — round 8
// mma.sync tf32 filter (tensor pipe, no tcgen05) + exact fp32 recheck.
// ---------------------------------------------------------------------------

constexpr int Dc = 256, Kc = 1024, Nrows = 16384, TM = 128;
constexpr float DECAYF = 0.99f, OMDF = 0.01f, EPSF = 1e-5f, KEPSF = 0.01024f;
constexpr float THETA = 2e-3f;     // > 2x hard |tf32 score - exact score| bound
constexpr int CAP = 24;

// ----- smem byte offsets (vq_main) -----
constexpr int SB_XP   = 0;                 // packed A tile: 8192 float4 = 128KB
constexpr int SB_WSQ  = 131072;            // 1024 f32 = 4KB
constexpr int SB_RMIN = 135168;            // 128 u32
constexpr int SB_CNT  = 135680;            // 128 i32
constexpr int SB_LIST = 136192;            // 128 x 24 i32 = 12KB
constexpr int SB_FIN  = 148480;            // 128 i32
constexpr int SB_RED  = 148992;            // 8 f32
constexpr int SMEM_MAIN = 149504;

// ----- device scratch (no allocations allowed) -----
__device__ float g_xsq[Nrows];
__device__ float g_wsq[Kc];
__device__ float g_wp[Kc * Dc];     // tf32 w, k-pair-packed: [n][k8*8+tig*2+h] = w[n][k8*8+tig+4h]
__device__ float g_dw[Kc * Dc];
__device__ float g_counts[Kc];
__device__ float g_loss;

__device__ __forceinline__ uint32_t encf(float x) {
  uint32_t u = __float_as_uint(x);
  return (u & 0x80000000u) ? ~u : (u | 0x80000000u);
}
__device__ __forceinline__ float decf(uint32_t e) {
  return (e & 0x80000000u) ? __uint_as_float(e ^ 0x80000000u) : __uint_as_float(~e);
}
__device__ __forceinline__ uint32_t tf32r(float x) {
  uint32_t t;
  asm("cvt.rna.tf32.f32 %0, %1;" : "=r"(t) : "f"(x));
  return t;
}

// ---------------------------------------------------------------------------
// Kernel 0: xsq/wsq (reduction BYTE-IDENTICAL to all passing rounds);
// build packed tf32 w; zero scatter scratch.
// ---------------------------------------------------------------------------
__global__ void prep_kernel(const float* __restrict__ x, const float* __restrict__ w) {
  int b = blockIdx.x, t = threadIdx.x;
  float v;
  if (b < Nrows) {
    v = x[(size_t)b * Dc + t];
  } else {
    int k = b - Nrows;
    v = w[(size_t)k * Dc + t];
    // packed pos: k8 = t>>3, tig = t&3, h = (t>>2)&1 -> p = k8*8 + tig*2 + h
    int p = ((t >> 3) << 3) + ((t & 3) << 1) + ((t >> 2) & 1);
    g_wp[(size_t)k * Dc + p] = __uint_as_float(tf32r(v));
    g_dw[(size_t)k * Dc + t] = 0.0f;
    if (t == 0) g_counts[k] = 0.0f;
    if (t == 1 && k == 0) g_loss = 0.0f;
  }
  float s = v * v;
  #pragma unroll
  for (int o = 16; o; o >>= 1) s += __shfl_down_sync(0xffffffffu, s, o);
  __shared__ float red[8];
  if ((t & 31) == 0) red[t >> 5] = s;
  __syncthreads();
  if (t == 0) {
    float tot = red[0];
    #pragma unroll
    for (int i = 1; i < 8; i++) tot += red[i];
    if (b < Nrows) g_xsq[b] = tot;
    else           g_wsq[b - Nrows] = tot;
  }
}

// ---------------------------------------------------------------------------
// Kernel 1: tf32 mma.sync GEMM filter + exact recheck + epilogue.
// 128 CTAs x 256 threads (8 warps: 2 row-halves x 4 col-groups).
// Warp microtile: m64 (4 m16 blocks) x n64 (8 n8 tiles) per chunk, 4 chunks.
// ---------------------------------------------------------------------------
__global__ void __launch_bounds__(256, 1)
vq_main(const float* __restrict__ x, const float* __restrict__ w,
        float* __restrict__ outQ) {
  extern __shared__ char smem[];
  float4* xp4 = reinterpret_cast<float4*>(smem + SB_XP);
  float*  sWsq = reinterpret_cast<float*>(smem + SB_WSQ);
  uint32_t* sRmin = reinterpret_cast<uint32_t*>(smem + SB_RMIN);
  int* sCnt  = reinterpret_cast<int*>(smem + SB_CNT);
  int* sList = reinterpret_cast<int*>(smem + SB_LIST);
  int* sFin  = reinterpret_cast<int*>(smem + SB_FIN);
  float* sRed = reinterpret_cast<float*>(smem + SB_RED);

  const int tid = threadIdx.x;
  const int lane = tid & 31;
  const int wid = tid >> 5;
  const int gid = lane >> 2;       // 0..7
  const int tig = lane & 3;        // 0..3
  const int rh = wid & 1;          // row half (64 rows)
  const int cg = wid >> 1;         // col group (256 cols)
  const int rowBase = blockIdx.x * TM;

  // ---- init small smem
  if (tid < 128) { sRmin[tid] = 0xFFFFFFFFu; sCnt[tid] = 0; }
  #pragma unroll
  for (int i = 0; i < 4; i++) sWsq[tid + 256 * i] = g_wsq[tid + 256 * i];

  // ---- pack A (x tf32) into smem:
  // float4 at ((mb*32+k8)*32 + tig*8 + gid) =
  //   ( x[mb*16+gid][k], x[mb*16+gid+8][k], x[..][k+4], x[..+8][k+4] ), k=k8*8+tig
  {
    int r = tid >> 1, half = tid & 1;
    int mb = r >> 4, e = (r >> 3) & 1, g = r & 7;
    const float4* src = reinterpret_cast<const float4*>(x + (size_t)(rowBase + r) * Dc)
                        + half * 32;
    float* xpf = reinterpret_cast<float*>(xp4);
    #pragma unroll
    for (int jj = 0; jj < 32; jj++) {
      float4 v = src[jj];
      int k0 = half * 128 + 4 * jj;
      int k8 = k0 >> 3, h = (k0 >> 2) & 1;
      int base = (mb * 32 + k8) * 128 + g * 4 + e + 2 * h;
      xpf[base + 0 * 32] = __uint_as_float(tf32r(v.x));
      xpf[base + 1 * 32] = __uint_as_float(tf32r(v.y));
      xpf[base + 2 * 32] = __uint_as_float(tf32r(v.z));
      xpf[base + 3 * 32] = __uint_as_float(tf32r(v.w));
    }
  }
  __syncthreads();

  // ---- GEMM filter: 4 chunks of 64 cols per warp
  for (int ch = 0; ch < 4; ch++) {
    const int cb = cg * 256 + ch * 64;
    const float2* bptr[8];
    #pragma unroll
    for (int nt = 0; nt < 8; nt++)
      bptr[nt] = reinterpret_cast<const float2*>(
          g_wp + (size_t)(cb + nt * 8 + gid) * Dc + tig * 2);

    float c[4][8][4];
    #pragma unroll
    for (int i = 0; i < 4; i++)
      #pragma unroll
      for (int j = 0; j < 8; j++)
        c[i][j][0] = c[i][j][1] = c[i][j][2] = c[i][j][3] = 0.0f;

    #pragma unroll 2
    for (int k8 = 0; k8 < 32; k8++) {
      float4 a[4];
      #pragma unroll
      for (int m = 0; m < 4; m++)
        a[m] = xp4[((rh * 4 + m) * 32 + k8) * 32 + tig * 8 + gid];
      float2 bv[8];
      #pragma unroll
      for (int nt = 0; nt < 8; nt++) bv[nt] = bptr[nt][k8 * 4];
      #pragma unroll
      for (int m = 0; m < 4; m++) {
        uint32_t a0 = __float_as_uint(a[m].x), a1 = __float_as_uint(a[m].y);
        uint32_t a2 = __float_as_uint(a[m].z), a3 = __float_as_uint(a[m].w);
        #pragma unroll
        for (int nt = 0; nt < 8; nt++) {
          asm volatile(
            "mma.sync.aligned.m16n8k8.row.col.f32.tf32.tf32.f32 "
            "{%0,%1,%2,%3},{%4,%5,%6,%7},{%8,%9},{%0,%1,%2,%3};"
            : "+f"(c[m][nt][0]), "+f"(c[m][nt][1]), "+f"(c[m][nt][2]), "+f"(c[m][nt][3])
            : "r"(a0), "r"(a1), "r"(a2), "r"(a3),
              "r"(__float_as_uint(bv[nt].x)), "r"(__float_as_uint(bv[nt].y)));
        }
      }
    }

    // ---- phase A: per-row shared running min (order-encoded atomicMin)
    #pragma unroll
    for (int m = 0; m < 4; m++) {
      float m0 = 3.4e38f, m1 = 3.4e38f;
      #pragma unroll
      for (int nt = 0; nt < 8; nt++) {
        int col0 = cb + nt * 8 + 2 * tig;
        float s0 = fmaf(-2.0f, c[m][nt][0], sWsq[col0]);
        float s1 = fmaf(-2.0f, c[m][nt][1], sWsq[col0 + 1]);
        float s2 = fmaf(-2.0f, c[m][nt][2], sWsq[col0]);
        float s3 = fmaf(-2.0f, c[m][nt][3], sWsq[col0 + 1]);
        m0 = fminf(m0, fminf(s0, s1));
        m1 = fminf(m1, fminf(s2, s3));
      }
      int r0 = (rh * 4 + m) * 16 + gid;
      atomicMin(&sRmin[r0], encf(m0));
      atomicMin(&sRmin[r0 + 8], encf(m1));
    }
    __syncthreads();

    // ---- phase B: collect candidates within THETA of (monotone) row min
    #pragma unroll
    for (int m = 0; m < 4; m++) {
      int r0 = (rh * 4 + m) * 16 + gid;
      float th0 = decf(sRmin[r0]) + THETA;
      float th1 = decf(sRmin[r0 + 8]) + THETA;
      #pragma unroll
      for (int nt = 0; nt < 8; nt++) {
        int col0 = cb + nt * 8 + 2 * tig;
        float s0 = fmaf(-2.0f, c[m][nt][0], sWsq[col0]);
        float s1 = fmaf(-2.0f, c[m][nt][1], sWsq[col0 + 1]);
        float s2 = fmaf(-2.0f, c[m][nt][2], sWsq[col0]);
        float s3 = fmaf(-2.0f, c[m][nt][3], sWsq[col0 + 1]);
        if (s0 < th0) { int p = atomicAdd(&sCnt[r0], 1);     if (p < CAP) sList[r0 * CAP + p] = col0; }
        if (s1 < th0) { int p = atomicAdd(&sCnt[r0], 1);     if (p < CAP) sList[r0 * CAP + p] = col0 + 1; }
        if (s2 < th1) { int p = atomicAdd(&sCnt[r0 + 8], 1); if (p < CAP) sList[(r0 + 8) * CAP + p] = col0; }
        if (s3 < th1) { int p = atomicAdd(&sCnt[r0 + 8], 1); if (p < CAP) sList[(r0 + 8) * CAP + p] = col0 + 1; }
      }
    }
    __syncthreads();
  }

  // ---- exact recheck (threads 0-127, row = tid); bit-identical score chain
  if (tid < 128) {
    int nc = sCnt[tid];
    if (nc > CAP) nc = CAP;
    int kbest = Kc;
    if (nc == 1) {
      kbest = sList[tid * CAP];
    } else {
      float xsq = g_xsq[rowBase + tid];
      const float4* xr = reinterpret_cast<const float4*>(x + (size_t)(rowBase + tid) * Dc);
      float bs = 3.4e38f;
      for (int i = 0; i < nc; i++) {
        int k = sList[tid * CAP + i];
        const float4* wr = reinterpret_cast<const float4*>(w + (size_t)k * Dc);
        float acc = 0.0f;
        #pragma unroll 8
        for (int d4 = 0; d4 < 64; d4++) {
          float4 xv = xr[d4], wv = wr[d4];
          acc = fmaf(xv.x, wv.x, acc);
          acc = fmaf(xv.y, wv.y, acc);
          acc = fmaf(xv.z, wv.z, acc);
          acc = fmaf(xv.w, wv.w, acc);
        }
        float r1 = __fadd_rn(xsq, sWsq[k]);
        float s  = __fadd_rn(r1, -2.0f * acc);
        if (s < bs || (s == bs && k < kbest)) { bs = s; kbest = k; }
      }
    }
    sFin[tid] = kbest;
    atomicAdd(&g_counts[kbest], 1.0f);
  }
  __syncthreads();

  // ---- epilogue: gather quantized rows, loss partial, dw scatter
  float lsum = 0.0f;
  {
    int q = tid & 63, rg = tid >> 6;
    #pragma unroll 4
    for (int it = 0; it < 32; ++it) {
      int row = rg * 32 + it;
      int k = sFin[row];
      float4 wv = *reinterpret_cast<const float4*>(w + (size_t)k * Dc + 4 * q);
      float4 xv = *reinterpret_cast<const float4*>(x + (size_t)(rowBase + row) * Dc + 4 * q);
      *reinterpret_cast<float4*>(outQ + (size_t)(rowBase + row) * Dc + 4 * q) = wv;
      float d0 = xv.x - wv.x, d1 = xv.y - wv.y, d2 = xv.z - wv.z, d3 = xv.w - wv.w;
      lsum += d0 * d0 + d1 * d1 + d2 * d2 + d3 * d3;
      float* dwp = g_dw + (size_t)k * Dc + 4 * q;
      atomicAdd(dwp + 0, xv.x);
      atomicAdd(dwp + 1, xv.y);
      atomicAdd(dwp + 2, xv.z);
      atomicAdd(dwp + 3, xv.w);
    }
  }
  #pragma unroll
  for (int o = 16; o; o >>= 1) lsum += __shfl_down_sync(0xffffffffu, lsum, o);
  if ((tid & 31) == 0) sRed[tid >> 5] = lsum;
  __syncthreads();
  if (tid == 0) {
    float tot = sRed[0];
    #pragma unroll
    for (int i = 1; i < 8; i++) tot += sRed[i];
    atomicAdd(&g_loss, tot);
  }
}

// ---------------------------------------------------------------------------
// Kernel 2: cluster-size EMA + Laplace + ema_w EMA + embed (validated).
// ---------------------------------------------------------------------------
__global__ void emacs_kernel(const float* __restrict__ ema_cs,
                             const float* __restrict__ ema_w,
                             float* __restrict__ outLoss, float* __restrict__ outEmbed,
                             float* __restrict__ outCS, float* __restrict__ outEmaW) {
  int k = blockIdx.x, d = threadIdx.x;
  __shared__ float red[8];
  __shared__ float s_cs;
  float4 v = reinterpret_cast<const float4*>(ema_cs)[d];
  float s = v.x + v.y + v.z + v.w;
  #pragma unroll
  for (int o = 16; o; o >>= 1) s += __shfl_down_sync(0xffffffffu, s, o);
  if ((d & 31) == 0) red[d >> 5] = s;
  __syncthreads();
  if (d == 0) {
    float S = red[0];
    #pragma unroll
    for (int i = 1; i < 8; i++) S += red[i];
    float n = DECAYF * S + OMDF * (float)Nrows;
    float c = ema_cs[k] * DECAYF + OMDF * g_counts[k];
    float csf = (c + EPSF) / (n + KEPSF) * n;
    s_cs = csf;
    outCS[k] = csf;
    if (k == 0) outLoss[0] = 0.25f * g_loss * (1.0f / 4194304.0f);
  }
  __syncthreads();
  size_t i = (size_t)k * Dc + d;
  float ew = ema_w[i] * DECAYF + OMDF * g_dw[i];
  outEmaW[i]  = ew;
  outEmbed[i] = ew / s_cs;
}

// ---------------------------------------------------------------------------
extern "C" void kernel_launch(void* const* d_in, const int* in_sizes, int n_in,
                              void* d_out, int out_size) {
  const float* x      = (const float*)d_in[0];
  const float* w      = (const float*)d_in[1];
  const float* ema_cs = (const float*)d_in[2];
  const float* ema_w  = (const float*)d_in[3];

  float* out      = (float*)d_out;
  float* outQ     = out;
  float* outLoss  = out + (size_t)Nrows * Dc;
  float* outEmbed = outLoss + 1;
  float* outCS    = outEmbed + (size_t)Kc * Dc;
  float* outEmaW  = outCS + Kc;

  cudaFuncSetAttribute(vq_main, cudaFuncAttributeMaxDynamicSharedMemorySize, SMEM_MAIN);

  prep_kernel<<<Nrows + Kc, 256>>>(x, w);
  vq_main<<<Nrows / TM, 256, SMEM_MAIN>>>(x, w, outQ);
  emacs_kernel<<<Kc, 256>>>(ema_cs, ema_w, outLoss, outEmbed, outCS, outEmaW);
}